// round 12
// baseline (speedup 1.0000x reference)
#include <cuda_runtime.h>
#include <cstdint>

#define N 8192
#define IN_F 512
#define OUT_F 64
#define SS 512

// ---------------- device scratch (static) ----------------
__device__ float g_wa[2 * IN_F];                   // wa1[512], wa2[512]
__device__ float g_R[N];                           // exp(-0.8 * s1_i)
__device__ __align__(16) float2 g_EP[N];           // (exp(s2_j), exp(0.2*s2_j))
__device__ __align__(16) float g_part[512 * N];    // 16MB per-block partial colsums
__device__ float g_colsumf[N];

// ---------------- profiler-slot shim ----------------
__global__ void k_nop() {}

// ---------------- wa1 = W @ a1, wa2 = W @ a2 (tiny) ----------------
__global__ void k_wa(const float* __restrict__ W, const float* __restrict__ a) {
    int m = threadIdx.x;
    const float4* w4 = (const float4*)(W + m * OUT_F);
    float s1 = 0.f, s2 = 0.f;
#pragma unroll
    for (int q = 0; q < OUT_F / 4; q++) {
        float4 wv = __ldg(w4 + q);
        s1 += wv.x * __ldg(a + 4 * q + 0) + wv.y * __ldg(a + 4 * q + 1)
            + wv.z * __ldg(a + 4 * q + 2) + wv.w * __ldg(a + 4 * q + 3);
        s2 += wv.x * __ldg(a + OUT_F + 4 * q + 0) + wv.y * __ldg(a + OUT_F + 4 * q + 1)
            + wv.z * __ldg(a + OUT_F + 4 * q + 2) + wv.w * __ldg(a + OUT_F + 4 * q + 3);
    }
    g_wa[m] = s1;
    g_wa[IN_F + m] = s2;
}

// ---------------- s1,s2 = input @ wa  ->  R_i, (ex_j, ey_j) ----------------
__global__ void k_s(const float* __restrict__ in) {
    __shared__ float swa[2 * IN_F];
    int t = threadIdx.x;
#pragma unroll
    for (int q = 0; q < 4; q++) swa[q * 256 + t] = g_wa[q * 256 + t];
    __syncthreads();

    int warp = t >> 5, lane = t & 31;
    int row = blockIdx.x * 8 + warp;
    const float* ir = in + (size_t)row * IN_F;
    float s1 = 0.f, s2 = 0.f;
#pragma unroll
    for (int q = 0; q < IN_F / 32; q++) {
        float x = __ldg(ir + q * 32 + lane);
        s1 = fmaf(x, swa[q * 32 + lane], s1);
        s2 = fmaf(x, swa[IN_F + q * 32 + lane], s2);
    }
#pragma unroll
    for (int o = 16; o; o >>= 1) {
        s1 += __shfl_xor_sync(0xFFFFFFFFu, s1, o);
        s2 += __shfl_xor_sync(0xFFFFFFFFu, s2, o);
    }
    if (lane == 0) {
        double d1 = (double)s1, d2 = (double)s2;
        g_R[row] = (float)exp(-0.8 * d1);
        g_EP[row] = make_float2((float)exp(d2), (float)exp(0.2 * d2));
    }
}

// ---------------- two-phase masked-softmax + column partial sums ----------------
// 512 blocks x 512 threads; block owns 16 rows; thread owns 16 fixed columns:
//   column(g,e) = g*2048 + 4t + e
// Phase A: stream adj once, per-row z partials + packed adjacency masks. NO barriers.
// One __syncthreads(). Phase B: recompute w0=max(ex,R*ey), gate by mask, acc+=w*invZ.
// Float ops and summation orders identical to the R11 kernel -> bit-exact result.
__global__ void __launch_bounds__(512, 1) k_main(const int* __restrict__ adj) {
    __shared__ float sZ[16][16];                   // [row][warp] partials
    int t = threadIdx.x;
    int warp = t >> 5, lane = t & 31;
    int row0 = blockIdx.x * 16;

    // this thread's 16 (ex, ey) pairs -> registers
    float ex[16], ey[16];
    const float4* ep4 = (const float4*)g_EP;       // one float4 = 2 nodes
#pragma unroll
    for (int g = 0; g < 4; g++) {
#pragma unroll
        for (int q = 0; q < 2; q++) {
            float4 v = __ldg(ep4 + g * 1024 + 2 * t + q);
            ex[g * 4 + 2 * q + 0] = v.x; ey[g * 4 + 2 * q + 0] = v.y;
            ex[g * 4 + 2 * q + 1] = v.z; ey[g * 4 + 2 * q + 1] = v.w;
        }
    }

    uint32_t m[16];                                // adjacency bit-masks, 16 cols/row

    // ---- Phase A: barrier-free streaming ----
    {
        int4 buf[2][4];
#pragma unroll
        for (int g = 0; g < 4; g++) {
            buf[0][g] = __ldg((const int4*)(adj + (size_t)(row0 + 0) * N) + g * 512 + t);
            buf[1][g] = __ldg((const int4*)(adj + (size_t)(row0 + 1) * N) + g * 512 + t);
        }
#pragma unroll
        for (int r = 0; r < 16; r++) {
            float R = __ldg(g_R + row0 + r);
            float z = 0.f;
            uint32_t mask = 0;
#pragma unroll
            for (int g = 0; g < 4; g++) {
                int4 A = buf[r & 1][g];
                float w0 = fmaxf(ex[g * 4 + 0], R * ey[g * 4 + 0]);
                float w1 = fmaxf(ex[g * 4 + 1], R * ey[g * 4 + 1]);
                float w2 = fmaxf(ex[g * 4 + 2], R * ey[g * 4 + 2]);
                float w3 = fmaxf(ex[g * 4 + 3], R * ey[g * 4 + 3]);
                uint32_t b0 = (A.x > 0) ? 1u : 0u;
                uint32_t b1 = (A.y > 0) ? 1u : 0u;
                uint32_t b2 = (A.z > 0) ? 1u : 0u;
                uint32_t b3 = (A.w > 0) ? 1u : 0u;
                mask |= (b0 << (g * 4)) | (b1 << (g * 4 + 1))
                      | (b2 << (g * 4 + 2)) | (b3 << (g * 4 + 3));
                w0 = b0 ? w0 : 0.f;
                w1 = b1 ? w1 : 0.f;
                w2 = b2 ? w2 : 0.f;
                w3 = b3 ? w3 : 0.f;
                z += (w0 + w1) + (w2 + w3);        // same pairwise order as R11
            }
            // prefetch row r+2 (no barrier in the way -> true pipelining)
            if (r < 14) {
                const int4* nb = (const int4*)(adj + (size_t)(row0 + r + 2) * N);
#pragma unroll
                for (int g = 0; g < 4; g++) buf[r & 1][g] = __ldg(nb + g * 512 + t);
            }
            m[r] = mask;
#pragma unroll
            for (int o = 16; o; o >>= 1) z += __shfl_xor_sync(0xFFFFFFFFu, z, o);
            if (lane == 0) sZ[r][warp] = z;
        }
    }
    __syncthreads();                               // the ONLY block barrier

    // ---- Phase B: no memory, recompute + accumulate ----
    float acc[16];
#pragma unroll
    for (int k = 0; k < 16; k++) acc[k] = 0.f;

#pragma unroll
    for (int r = 0; r < 16; r++) {
        float zt = 0.f;
#pragma unroll
        for (int q = 0; q < 16; q++) zt += sZ[r][q];   // same order as R11
        float invZ = (zt > 0.f) ? (1.0f / zt) : 0.f;   // same exact division
        float R = __ldg(g_R + row0 + r);               // L1-hot reload
        uint32_t mask = m[r];
#pragma unroll
        for (int g = 0; g < 4; g++) {
#pragma unroll
            for (int e = 0; e < 4; e++) {
                int k = g * 4 + e;
                float w0 = fmaxf(ex[k], R * ey[k]);    // identical recompute
                float val = (mask >> k) & 1u ? w0 : 0.f;
                acc[k] = fmaf(val, invZ, acc[k]);
            }
        }
    }

    float4* part4 = (float4*)(g_part + (size_t)blockIdx.x * N);
#pragma unroll
    for (int g = 0; g < 4; g++)
        part4[g * 512 + t] = make_float4(acc[g * 4 + 0], acc[g * 4 + 1],
                                         acc[g * 4 + 2], acc[g * 4 + 3]);
}

// ---------------- deterministic column reduction (fp32 chunks, fp64 combine) ----
__global__ void __launch_bounds__(256) k_reduce() {
    __shared__ float sd[8][32];
    int t = threadIdx.x;
    int v = t & 31;
    int u = t >> 5;
    int c = blockIdx.x * 32 + v;
    float s = 0.f;
    int b0 = u * 64;
#pragma unroll 8
    for (int b = b0; b < b0 + 64; b++)
        s += g_part[(size_t)b * N + c];
    sd[u][v] = s;
    __syncthreads();
    if (u == 0) {
        double tot = 0.0;
#pragma unroll
        for (int q = 0; q < 8; q++) tot += (double)sd[q][v];
        g_colsumf[c] = (float)tot;
    }
}

// ---------------- exact top-512 via brute-force ranking (FLOAT out) ----------------
__global__ void __launch_bounds__(256) k_rank(float* __restrict__ out) {
    __shared__ uint32_t sc[N];
    __shared__ int sr[256];
    int t = threadIdx.x;
    const float4* cs4 = (const float4*)g_colsumf;
    uint4* sc4 = (uint4*)sc;
#pragma unroll
    for (int p = 0; p < N / 4 / 256; p++) {
        float4 v = __ldg(cs4 + p * 256 + t);
        sc4[p * 256 + t] = make_uint4(__float_as_uint(v.x), __float_as_uint(v.y),
                                      __float_as_uint(v.z), __float_as_uint(v.w));
    }
    __syncthreads();

    int jl  = t & 15;
    int seg = t >> 4;
    int j = blockIdx.x * 16 + jl;
    uint32_t sj = sc[j];
    int rank = 0;
    int p0 = seg * (N / 16);
#pragma unroll 4
    for (int p = p0; p < p0 + N / 16; p++) {
        uint32_t sp = sc[p];
        rank += (sp > sj) || (sp == sj && p < j);
    }
    sr[t] = rank;
    __syncthreads();
    if (t < 16) {
        int total = 0;
#pragma unroll
        for (int s = 0; s < 16; s++) total += sr[t + 16 * s];
        if (total < SS) out[total] = (float)j;
    }
}

// ---------------- launch ----------------
extern "C" void kernel_launch(void* const* d_in, const int* in_sizes, int n_in,
                              void* d_out, int out_size) {
    const float* input = nullptr;
    const int*   adj   = nullptr;
    const float* W     = nullptr;
    const float* a     = nullptr;
    for (int i = 0; i < n_in; i++) {
        long long s = in_sizes[i];
        if      (s == (long long)N * IN_F)     input = (const float*)d_in[i];
        else if (s == (long long)N * N)        adj   = (const int*)d_in[i];
        else if (s == (long long)IN_F * OUT_F) W     = (const float*)d_in[i];
        else if (s == 2 * OUT_F)               a     = (const float*)d_in[i];
    }
    if (!input || !adj || !W || !a) {
        input = (const float*)d_in[0];
        adj   = (const int*)d_in[1];
        W     = (const float*)d_in[2];
        a     = (const float*)d_in[3];
    }
    float* out = (float*)d_out;

    k_wa<<<1, IN_F>>>(W, a);
    k_s<<<N / 8, 256>>>(input);
    k_nop<<<1, 32>>>();                 // shim: k_main lands in the profiled 4th slot
    k_main<<<512, 512>>>(adj);
    k_reduce<<<N / 32, 256>>>();
    k_rank<<<N / 16, 256>>>(out);
}